// round 5
// baseline (speedup 1.0000x reference)
#include <cuda_runtime.h>
#include <math.h>

#define Dm   256
#define Lw   32
#define Mm   4096
#define Cc   4096
#define NROWS (Mm + 1)          // 4097 memory rows (mems + xs)
#define NB   64                 // partial blocks for deterministic weighted sum
#define EPSV 1e-8f

// ---- scratch (no allocation allowed; __device__ globals) ----
__device__ float g_mems_enc[(size_t)NROWS * Dm];   // 4.2 MB
__device__ float g_cos[NROWS];
__device__ float g_att[NROWS];                     // unnormalized exp()
__device__ float g_attsum;
__device__ float g_partial[NB * Dm];
__device__ float g_lhs[Dm];

__inline__ __device__ float warpReduceSum(float v) {
#pragma unroll
    for (int o = 16; o > 0; o >>= 1) v += __shfl_xor_sync(0xffffffffu, v, o);
    return v;
}
__inline__ __device__ float warpReduceMax(float v) {
#pragma unroll
    for (int o = 16; o > 0; o >>= 1) v = fmaxf(v, __shfl_xor_sync(0xffffffffu, v, o));
    return v;
}

// ============================================================================
// Kernel 1: encoder. One block per token row (256 threads = D).
//   bid 0          : xs    -> g_mems_enc row Mm (appended xs_emb)
//   bid 1..Mm      : mems  -> g_mems_enc rows 0..Mm-1
//   bid Mm+1       : ys    -> outY row 0
//   bid Mm+2..     : cands -> outY rows 1..Cc
// out = (1/||w||) * sum_l freqs[tok_l] * lt[tok_l][d]
// ============================================================================
__global__ void encode_kernel(const int* __restrict__ xs,
                              const int* __restrict__ mems,
                              const int* __restrict__ ys,
                              const int* __restrict__ cands,
                              const float* __restrict__ lt,
                              const float* __restrict__ freqs,
                              float* __restrict__ outY) {
    __shared__ int   stok[Lw];
    __shared__ float sw[Lw];
    __shared__ float sinv;

    const int bid = blockIdx.x;
    const int* tok;
    float* dst;
    if (bid == 0)            { tok = xs;                           dst = g_mems_enc + (size_t)Mm * Dm; }
    else if (bid <= Mm)      { tok = mems  + (bid - 1) * Lw;       dst = g_mems_enc + (size_t)(bid - 1) * Dm; }
    else if (bid == Mm + 1)  { tok = ys;                           dst = outY; }
    else                     { tok = cands + (bid - (Mm + 2)) * Lw; dst = outY + (size_t)(bid - (Mm + 1)) * Dm; }

    const int t = threadIdx.x;
    if (t < Lw) {
        int   tk = tok[t];
        float w  = freqs[tk];
        stok[t] = tk;
        sw[t]   = w;
        float s = w * w;
        s = warpReduceSum(s);
        if (t == 0) sinv = 1.0f / sqrtf(s);
    }
    __syncthreads();

    float acc = 0.0f;
#pragma unroll
    for (int l = 0; l < Lw; ++l) {
        acc = fmaf(sw[l], __ldg(&lt[(size_t)stok[l] * Dm + t]), acc);
    }
    dst[t] = acc * sinv;
}

// ============================================================================
// Kernel 2: cosine similarity of each memory row vs xs_emb (row Mm).
// ============================================================================
__global__ void cos_kernel() {
    const int i = blockIdx.x;
    const int t = threadIdx.x;
    const int w = t >> 5, lane = t & 31;

    float a = g_mems_enc[(size_t)Mm * Dm + t];
    float b = g_mems_enc[(size_t)i  * Dm + t];
    float dot = a * b, a2 = a * a, b2 = b * b;

    __shared__ float sd[8], sa[8], sb[8];
    dot = warpReduceSum(dot); a2 = warpReduceSum(a2); b2 = warpReduceSum(b2);
    if (lane == 0) { sd[w] = dot; sa[w] = a2; sb[w] = b2; }
    __syncthreads();
    if (w == 0) {
        dot = (lane < 8) ? sd[lane] : 0.0f;
        a2  = (lane < 8) ? sa[lane] : 0.0f;
        b2  = (lane < 8) ? sb[lane] : 0.0f;
        dot = warpReduceSum(dot); a2 = warpReduceSum(a2); b2 = warpReduceSum(b2);
        if (lane == 0) {
            float an = fmaxf(sqrtf(a2), EPSV);
            float bn = fmaxf(sqrtf(b2), EPSV);
            g_cos[i] = dot / (an * bn);
        }
    }
}

// ============================================================================
// Kernel 3: softmax numerator over 4097 values. Stores exp(c - max) and sum.
// (Normalization is folded into sum_lhs: lhs = (Σ e_i enc_i) / Σ e_i.)
// ============================================================================
__global__ void softmax_kernel() {
    const int t = threadIdx.x;          // 512 threads
    const int w = t >> 5, lane = t & 31;
    __shared__ float sred[16];
    __shared__ float s_max, s_sum;

    float m = -1e30f;
    for (int i = t; i < NROWS; i += 512) m = fmaxf(m, g_cos[i]);
    m = warpReduceMax(m);
    if (lane == 0) sred[w] = m;
    __syncthreads();
    if (t == 0) {
        float mm = sred[0];
#pragma unroll
        for (int k = 1; k < 16; ++k) mm = fmaxf(mm, sred[k]);
        s_max = mm;
    }
    __syncthreads();

    float local = 0.0f;
    const float mx = s_max;
    for (int i = t; i < NROWS; i += 512) {
        float e = __expf(g_cos[i] - mx);
        g_att[i] = e;
        local += e;
    }
    local = warpReduceSum(local);
    if (lane == 0) sred[w] = local;
    __syncthreads();
    if (t == 0) {
        float ss = 0.0f;
#pragma unroll
        for (int k = 0; k < 16; ++k) ss += sred[k];
        g_attsum = ss;
        s_sum = ss;  (void)s_sum;
    }
}

// ============================================================================
// Kernel 4: deterministic partial attention-weighted sums.
// Block b owns rows {b, b+NB, b+2NB, ...} in fixed order.
// ============================================================================
__global__ void weighted_kernel() {
    const int b = blockIdx.x;
    const int t = threadIdx.x;
    float acc = 0.0f;
    for (int i = b; i < NROWS; i += NB) {
        acc = fmaf(g_att[i], g_mems_enc[(size_t)i * Dm + t], acc);
    }
    g_partial[b * Dm + t] = acc;
}

// ============================================================================
// Kernel 5: reduce partials (fixed order) and apply softmax denominator.
// ============================================================================
__global__ void sumlhs_kernel() {
    const int t = threadIdx.x;
    float s = 0.0f;
#pragma unroll
    for (int b = 0; b < NB; ++b) s += g_partial[b * Dm + t];
    g_lhs[t] = s / g_attsum;
}

// ============================================================================
// Kernel 6: broadcast lhs into 4097 xs_out rows.
// ============================================================================
__global__ void tile_kernel(float* __restrict__ outX) {
    const int idx = blockIdx.x * blockDim.x + threadIdx.x;
    if (idx < NROWS * Dm) outX[idx] = g_lhs[idx & (Dm - 1)];
}

extern "C" void kernel_launch(void* const* d_in, const int* in_sizes, int n_in,
                              void* d_out, int out_size) {
    const int*   xs    = (const int*)d_in[0];
    const int*   mems  = (const int*)d_in[1];
    const int*   ys    = (const int*)d_in[2];
    const int*   cands = (const int*)d_in[3];
    const float* lt    = (const float*)d_in[4];
    const float* freqs = (const float*)d_in[5];

    float* out  = (float*)d_out;                    // xs_out first
    float* outY = out + (size_t)NROWS * Dm;         // then ys_out

    encode_kernel<<<2 + Mm + Cc, Dm>>>(xs, mems, ys, cands, lt, freqs, outY);
    cos_kernel<<<NROWS, Dm>>>();
    softmax_kernel<<<1, 512>>>();
    weighted_kernel<<<NB, Dm>>>();
    sumlhs_kernel<<<1, Dm>>>();
    const int total = NROWS * Dm;
    tile_kernel<<<(total + 255) / 256, 256>>>(out);
}

// round 6
// speedup vs baseline: 1.2417x; 1.2417x over previous
#include <cuda_runtime.h>
#include <math.h>

#define Dm    256
#define D4    64                 // Dm / 4
#define Lw    32
#define Mm    4096
#define Cc    4096
#define NROWS (Mm + 1)           // 4097 memory rows (mems + appended xs)
#define NBW   256                // blocks in fused attention-weighted pass
#define EPSV  1e-8f

// ---- scratch (__device__ globals; no allocation allowed) ----
__device__ float g_mems_enc[(size_t)NROWS * Dm];   // 4.2 MB encoded memories (+xs at row Mm)
__device__ float g_partial[NBW * Dm];              // per-block weighted partial sums
__device__ float g_attpart[NBW];                   // per-block exp-sum partials
__device__ float g_lhs[Dm];                        // final attention-weighted vector

__inline__ __device__ float warpReduceSum(float v) {
#pragma unroll
    for (int o = 16; o > 0; o >>= 1) v += __shfl_xor_sync(0xffffffffu, v, o);
    return v;
}

// ============================================================================
// Kernel 1: encoder, float4-vectorized. 64 threads/block, one block per row.
//   bid 0          : xs    -> g_mems_enc row Mm
//   bid 1..Mm      : mems  -> g_mems_enc rows 0..Mm-1
//   bid Mm+1       : ys    -> outY row 0
//   bid Mm+2..     : cands -> outY rows 1..Cc
// out = (1/||w||) * sum_l freqs[tok_l] * lt[tok_l][:]
// ============================================================================
__global__ void __launch_bounds__(D4) encode_kernel(
        const int* __restrict__ xs,   const int* __restrict__ mems,
        const int* __restrict__ ys,   const int* __restrict__ cands,
        const float4* __restrict__ lt4, const float* __restrict__ freqs,
        float4* __restrict__ outY4) {
    __shared__ int   stok[Lw];
    __shared__ float sw[Lw];
    __shared__ float sinv;

    const int bid = blockIdx.x;
    const int t   = threadIdx.x;            // 0..63 : float4 column
    const int* tok;
    float4* dst;
    float4* enc4 = (float4*)g_mems_enc;
    if (bid == 0)            { tok = xs;                            dst = enc4 + (size_t)Mm * D4; }
    else if (bid <= Mm)      { tok = mems  + (bid - 1) * Lw;        dst = enc4 + (size_t)(bid - 1) * D4; }
    else if (bid == Mm + 1)  { tok = ys;                            dst = outY4; }
    else                     { tok = cands + (bid - (Mm + 2)) * Lw; dst = outY4 + (size_t)(bid - (Mm + 1)) * D4; }

    if (t < Lw) {
        int   tk = tok[t];
        float w  = freqs[tk];
        stok[t] = tk;
        sw[t]   = w;
        float s = warpReduceSum(w * w);
        if (t == 0) sinv = 1.0f / sqrtf(s);
    }
    __syncthreads();

    float4 acc = make_float4(0.f, 0.f, 0.f, 0.f);
#pragma unroll
    for (int l = 0; l < Lw; ++l) {
        float  w = sw[l];
        float4 v = __ldg(&lt4[(size_t)stok[l] * D4 + t]);
        acc.x = fmaf(w, v.x, acc.x);
        acc.y = fmaf(w, v.y, acc.y);
        acc.z = fmaf(w, v.z, acc.z);
        acc.w = fmaf(w, v.w, acc.w);
    }
    const float s = sinv;
    acc.x *= s; acc.y *= s; acc.z *= s; acc.w *= s;
    dst[t] = acc;
}

// ============================================================================
// Kernel 2 (fused): cosine + exp + attention-weighted partial sums.
// cos in [-1, 1] so exp(cos) needs no max-subtraction; softmax denominator is
// folded into the final reduce. Block b owns rows {b, b+NBW, ...} (fixed order
// -> deterministic). Per row: two-level block reduce of (dot, ||v||^2), then
// e = exp(cos), acc += e * v.
// ============================================================================
__global__ void __launch_bounds__(Dm) cosw_kernel() {
    const int b = blockIdx.x;
    const int t = threadIdx.x;              // 0..255, one dim each
    const int w = t >> 5, lane = t & 31;

    __shared__ float sr1[8], sr2[8];
    __shared__ float s_an, s_e;

    const float a = g_mems_enc[(size_t)Mm * Dm + t];   // xs_emb[t]

    // ||a|| once
    {
        float a2 = warpReduceSum(a * a);
        if (lane == 0) sr1[w] = a2;
        __syncthreads();
        if (t == 0) {
            float s = 0.f;
#pragma unroll
            for (int k = 0; k < 8; ++k) s += sr1[k];
            s_an = fmaxf(sqrtf(s), EPSV);
        }
        __syncthreads();
    }
    const float an = s_an;

    float acc  = 0.0f;
    float esum = 0.0f;
    for (int i = b; i < NROWS; i += NBW) {
        float v  = g_mems_enc[(size_t)i * Dm + t];
        float d1 = warpReduceSum(a * v);
        float d2 = warpReduceSum(v * v);
        if (lane == 0) { sr1[w] = d1; sr2[w] = d2; }
        __syncthreads();
        if (t == 0) {
            float dot = 0.f, b2 = 0.f;
#pragma unroll
            for (int k = 0; k < 8; ++k) { dot += sr1[k]; b2 += sr2[k]; }
            float bn = fmaxf(sqrtf(b2), EPSV);
            s_e = __expf(dot / (an * bn));
        }
        __syncthreads();
        float e = s_e;
        acc = fmaf(e, v, acc);
        if (t == 0) esum += e;
    }
    g_partial[b * Dm + t] = acc;
    if (t == 0) g_attpart[b] = esum;
}

// ============================================================================
// Kernel 3: reduce NBW partials (fixed order) + denominator -> g_lhs.
// 1024 threads: d = t&255, chunk c = t>>8 handles b = c, c+4, ...
// ============================================================================
__global__ void __launch_bounds__(1024) sumlhs_kernel() {
    const int t = threadIdx.x;
    __shared__ float ssum[8];
    __shared__ float s_att;
    __shared__ float spart[1024];

    // attention denominator (threads 0..255 hold one partial each)
    float ap = (t < NBW) ? g_attpart[t] : 0.0f;
    ap = warpReduceSum(ap);
    if ((t & 31) == 0) ssum[t >> 5] = ap;
    __syncthreads();
    if (t == 0) {
        float s = 0.f;
#pragma unroll
        for (int k = 0; k < 8; ++k) s += ssum[k];
        s_att = s;
    }

    const int d = t & (Dm - 1);
    const int c = t >> 8;                   // 0..3
    float s = 0.0f;
#pragma unroll 8
    for (int bb = c; bb < NBW; bb += 4)     // 64 iters, fixed order per chunk
        s += g_partial[bb * Dm + d];
    spart[t] = s;
    __syncthreads();
    if (c == 0) {
        float tot = spart[d] + spart[256 + d] + spart[512 + d] + spart[768 + d];
        g_lhs[d] = tot / s_att;
    }
}

// ============================================================================
// Kernel 4: broadcast lhs into 4097 xs_out rows (float4 stores).
// ============================================================================
__global__ void tile_kernel(float4* __restrict__ outX4) {
    const int idx = blockIdx.x * blockDim.x + threadIdx.x;
    if (idx < NROWS * D4) {
        const float4* lhs4 = (const float4*)g_lhs;
        outX4[idx] = __ldg(&lhs4[idx & (D4 - 1)]);
    }
}

extern "C" void kernel_launch(void* const* d_in, const int* in_sizes, int n_in,
                              void* d_out, int out_size) {
    const int*    xs    = (const int*)d_in[0];
    const int*    mems  = (const int*)d_in[1];
    const int*    ys    = (const int*)d_in[2];
    const int*    cands = (const int*)d_in[3];
    const float4* lt4   = (const float4*)d_in[4];
    const float*  freqs = (const float*)d_in[5];

    float* out   = (float*)d_out;                       // xs_out first
    float4* outY4 = (float4*)(out + (size_t)NROWS * Dm); // then ys_out

    encode_kernel<<<2 + Mm + Cc, D4>>>(xs, mems, ys, cands, lt4, freqs, outY4);
    cosw_kernel<<<NBW, Dm>>>();
    sumlhs_kernel<<<1, 1024>>>();
    const int tot4 = NROWS * D4;
    tile_kernel<<<(tot4 + 255) / 256, 256>>>((float4*)out);
}

// round 10
// speedup vs baseline: 1.5870x; 1.2781x over previous
#include <cuda_runtime.h>
#include <math.h>

#define Dm    256
#define D4    64                 // Dm / 4
#define Lw    32
#define Mm    4096
#define Cc    4096
#define NROWS (Mm + 1)           // 4097 memory rows (mems + appended xs)
#define NBW   256                // blocks in fused attention-weighted pass
#define WPB   8                  // warps per block in cosw
#define TOTW  (NBW * WPB)        // 2048 warps total
#define EPSV  1e-8f

// ---- scratch (__device__ globals; no allocation allowed) ----
__device__ float g_mems_enc[(size_t)NROWS * Dm];   // 4.2 MB encoded memories (+xs at row Mm)
__device__ float g_partial[NBW * Dm];              // per-block weighted partial sums
__device__ float g_attpart[NBW];                   // per-block exp-sum partials
__device__ float g_lhs[Dm];                        // final attention-weighted vector

__inline__ __device__ float warpReduceSum(float v) {
#pragma unroll
    for (int o = 16; o > 0; o >>= 1) v += __shfl_xor_sync(0xffffffffu, v, o);
    return v;
}

// ============================================================================
// Kernel 1: encoder, float4-vectorized. 64 threads/block, one block per row.
//   bid 0          : xs    -> g_mems_enc row Mm
//   bid 1..Mm      : mems  -> g_mems_enc rows 0..Mm-1
//   bid Mm+1       : ys    -> outY row 0
//   bid Mm+2..     : cands -> outY rows 1..Cc
// ============================================================================
__global__ void __launch_bounds__(D4) encode_kernel(
        const int* __restrict__ xs,   const int* __restrict__ mems,
        const int* __restrict__ ys,   const int* __restrict__ cands,
        const float4* __restrict__ lt4, const float* __restrict__ freqs,
        float4* __restrict__ outY4) {
    __shared__ int   stok[Lw];
    __shared__ float sw[Lw];
    __shared__ float sinv;

    const int bid = blockIdx.x;
    const int t   = threadIdx.x;            // 0..63 : float4 column
    const int* tok;
    float4* dst;
    float4* enc4 = (float4*)g_mems_enc;
    if (bid == 0)            { tok = xs;                            dst = enc4 + (size_t)Mm * D4; }
    else if (bid <= Mm)      { tok = mems  + (bid - 1) * Lw;        dst = enc4 + (size_t)(bid - 1) * D4; }
    else if (bid == Mm + 1)  { tok = ys;                            dst = outY4; }
    else                     { tok = cands + (bid - (Mm + 2)) * Lw; dst = outY4 + (size_t)(bid - (Mm + 1)) * D4; }

    if (t < Lw) {
        int   tk = tok[t];
        float w  = freqs[tk];
        stok[t] = tk;
        sw[t]   = w;
        float s = warpReduceSum(w * w);
        if (t == 0) sinv = 1.0f / sqrtf(s);
    }
    __syncthreads();

    float4 acc = make_float4(0.f, 0.f, 0.f, 0.f);
#pragma unroll
    for (int l = 0; l < Lw; ++l) {
        float  w = sw[l];
        float4 v = __ldg(&lt4[(size_t)stok[l] * D4 + t]);
        acc.x = fmaf(w, v.x, acc.x);
        acc.y = fmaf(w, v.y, acc.y);
        acc.z = fmaf(w, v.z, acc.z);
        acc.w = fmaf(w, v.w, acc.w);
    }
    const float s = sinv;
    acc.x *= s; acc.y *= s; acc.z *= s; acc.w *= s;
    dst[t] = acc;
}

// ============================================================================
// Kernel 2 (fused, warp-per-row): cosine + exp + attention-weighted partials.
// 8 warps/block; warp g = b*WPB + w owns rows {g, g+TOTW, ...} (deterministic
// fixed order). Each lane holds 8 dims (two float4 at cols lane and lane+32).
// All reductions are warp shuffles — no __syncthreads in the row loop.
// cos in [-1,1] so exp needs no max-subtraction; denominator folded into the
// final reduce. Block epilogue: fixed-order 8-warp combine via smem.
// ============================================================================
__global__ void __launch_bounds__(NBW) cosw_kernel() {
    const int b    = blockIdx.x;
    const int t    = threadIdx.x;
    const int w    = t >> 5;
    const int lane = t & 31;
    const int g    = b * WPB + w;           // global warp id

    const float4* enc4 = (const float4*)g_mems_enc;

    // xs_emb: each lane holds cols lane, lane+32 (float4 units)
    float4 a0 = enc4[(size_t)Mm * D4 + lane];
    float4 a1 = enc4[(size_t)Mm * D4 + lane + 32];
    float an;
    {
        float a2 = a0.x*a0.x + a0.y*a0.y + a0.z*a0.z + a0.w*a0.w
                 + a1.x*a1.x + a1.y*a1.y + a1.z*a1.z + a1.w*a1.w;
        a2 = warpReduceSum(a2);
        an = fmaxf(sqrtf(a2), EPSV);
    }

    float4 acc0 = make_float4(0.f,0.f,0.f,0.f);
    float4 acc1 = make_float4(0.f,0.f,0.f,0.f);
    float  esum = 0.0f;

    for (int i = g; i < NROWS; i += TOTW) {
        float4 v0 = enc4[(size_t)i * D4 + lane];
        float4 v1 = enc4[(size_t)i * D4 + lane + 32];
        float dot = a0.x*v0.x + a0.y*v0.y + a0.z*v0.z + a0.w*v0.w
                  + a1.x*v1.x + a1.y*v1.y + a1.z*v1.z + a1.w*v1.w;
        float b2  = v0.x*v0.x + v0.y*v0.y + v0.z*v0.z + v0.w*v0.w
                  + v1.x*v1.x + v1.y*v1.y + v1.z*v1.z + v1.w*v1.w;
        dot = warpReduceSum(dot);
        b2  = warpReduceSum(b2);
        float bn = fmaxf(sqrtf(b2), EPSV);
        float e  = __expf(dot / (an * bn));
        acc0.x = fmaf(e, v0.x, acc0.x); acc0.y = fmaf(e, v0.y, acc0.y);
        acc0.z = fmaf(e, v0.z, acc0.z); acc0.w = fmaf(e, v0.w, acc0.w);
        acc1.x = fmaf(e, v1.x, acc1.x); acc1.y = fmaf(e, v1.y, acc1.y);
        acc1.z = fmaf(e, v1.z, acc1.z); acc1.w = fmaf(e, v1.w, acc1.w);
        esum += e;
    }

    // block combine: 8 warps -> one partial row, fixed order (deterministic)
    __shared__ float4 sacc[WPB][2][32];     // 8 KB
    __shared__ float  ses[WPB];
    sacc[w][0][lane] = acc0;
    sacc[w][1][lane] = acc1;
    if (lane == 0) ses[w] = esum;
    __syncthreads();

    // 256 threads: thread t sums over warps 0..7 for its (half, lane) slot
    const int half = (t >> 5) & 1;          // warps 0..3 -> half of layout below
    // simpler: thread t handles float4 column c = t & 63, half = c>=32
    const int c  = t & 63;
    const int hh = (c >= 32) ? 1 : 0;
    const int ll = c & 31;
    float4 tot = make_float4(0.f,0.f,0.f,0.f);
#pragma unroll
    for (int k = 0; k < WPB; ++k) {
        float4 p = sacc[k][hh][ll];
        tot.x += p.x; tot.y += p.y; tot.z += p.z; tot.w += p.w;
    }
    if (t < 64) {   // only 64 distinct columns; threads 64..255 redundant
        ((float4*)g_partial)[b * D4 + c] = tot;
    }
    if (t == 0) {
        float es = 0.f;
#pragma unroll
        for (int k = 0; k < WPB; ++k) es += ses[k];
        g_attpart[b] = es;
    }
    (void)half;
}

// ============================================================================
// Kernel 3: reduce NBW partials (fixed order) + denominator -> g_lhs.
// ============================================================================
__global__ void __launch_bounds__(1024) sumlhs_kernel() {
    const int t = threadIdx.x;
    __shared__ float ssum[8];
    __shared__ float s_att;
    __shared__ float spart[1024];

    float ap = (t < NBW) ? g_attpart[t] : 0.0f;
    ap = warpReduceSum(ap);
    if ((t & 31) == 0) ssum[t >> 5] = ap;
    __syncthreads();
    if (t == 0) {
        float s = 0.f;
#pragma unroll
        for (int k = 0; k < 8; ++k) s += ssum[k];
        s_att = s;
    }

    const int d = t & (Dm - 1);
    const int c = t >> 8;                   // 0..3
    float s = 0.0f;
#pragma unroll 8
    for (int bb = c; bb < NBW; bb += 4)
        s += g_partial[bb * Dm + d];
    spart[t] = s;
    __syncthreads();
    if (c == 0) {
        float tot = spart[d] + spart[256 + d] + spart[512 + d] + spart[768 + d];
        g_lhs[d] = tot / s_att;
    }
}

// ============================================================================
// Kernel 4: broadcast lhs into 4097 xs_out rows.
// Grid-stride of 65536 float4 (multiple of 64) => idx & 63 constant per
// thread: ONE g_lhs register load, then a pure STG.128 loop.
// ============================================================================
__global__ void __launch_bounds__(256) tile_kernel(float4* __restrict__ outX4) {
    const int tid   = blockIdx.x * blockDim.x + threadIdx.x;   // 0..65535
    const int total = NROWS * D4;                              // 262208
    const float4 v  = __ldg(&((const float4*)g_lhs)[tid & (D4 - 1)]);
#pragma unroll 4
    for (int idx = tid; idx < total; idx += 256 * 256)
        outX4[idx] = v;
}

extern "C" void kernel_launch(void* const* d_in, const int* in_sizes, int n_in,
                              void* d_out, int out_size) {
    const int*    xs    = (const int*)d_in[0];
    const int*    mems  = (const int*)d_in[1];
    const int*    ys    = (const int*)d_in[2];
    const int*    cands = (const int*)d_in[3];
    const float4* lt4   = (const float4*)d_in[4];
    const float*  freqs = (const float*)d_in[5];

    float*  out   = (float*)d_out;                        // xs_out first
    float4* outY4 = (float4*)(out + (size_t)NROWS * Dm);  // then ys_out

    encode_kernel<<<2 + Mm + Cc, D4>>>(xs, mems, ys, cands, lt4, freqs, outY4);
    cosw_kernel<<<NBW, NBW>>>();
    sumlhs_kernel<<<1, 1024>>>();
    tile_kernel<<<256, 256>>>((float4*)out);
}